// round 15
// baseline (speedup 1.0000x reference)
#include <cuda_runtime.h>
#include <cuda_fp16.h>
#include <cstdint>

#define TT 4096
#define HH 2048
#define DD 2048
#define EE 16
#define EH 8             // experts per gemm1 half-launch
#define KTOP 4
#define ALPHA_C 1.702f
#define LIMIT_C 7.0f
#define BK 32
#define NC (HH / BK)     // 64 (HH == DD)

// GEMM1 dynamic smem: A 4*10240, Bg 4*4096, Bu 4*4096, tok 512
#define G1_A_OFF   0
#define G1_BG_OFF  (4 * 10240)
#define G1_BU_OFF  (G1_BG_OFF + 4 * 4096)
#define G1_TOK_OFF (G1_BU_OFF + 4 * 4096)
#define G1_SMEM    (G1_TOK_OFF + 512)
// GEMM2 dynamic smem: A 4*10240, B 4*8192, tok 512, wts 512
#define G2_A_OFF   0
#define G2_B_OFF   (4 * 10240)
#define G2_TOK_OFF (G2_B_OFF + 4 * 8192)
#define G2_WTS_OFF (G2_TOK_OFF + 512)
#define G2_SMEM    (G2_WTS_OFF + 512)

// ---------------- device scratch ----------------
__device__ int    g_cnt[EE];
__device__ int    g_rows[EE * TT];
__device__ float  g_wte[EE * TT];
__device__ __half g_xh[(size_t)TT * HH];
__device__ __half g_wguH[(size_t)EE * HH * (2 * DD)];
__device__ __half g_dpH[(size_t)EE * DD * HH];
__device__ __half g_gatedH[(size_t)EE * TT * DD];

// ---------------- helpers ----------------
__device__ __forceinline__ uint32_t smem_u32(const void* p) {
    uint32_t a;
    asm("{ .reg .u64 t; cvta.to.shared.u64 t, %1; cvt.u32.u64 %0, t; }" : "=r"(a) : "l"(p));
    return a;
}
__device__ __forceinline__ void ldsm4(uint32_t* r, uint32_t addr) {
    asm volatile("ldmatrix.sync.aligned.m8n8.x4.shared.b16 {%0,%1,%2,%3}, [%4];"
        : "=r"(r[0]), "=r"(r[1]), "=r"(r[2]), "=r"(r[3]) : "r"(addr));
}
__device__ __forceinline__ void ldsm2t(uint32_t& r0, uint32_t& r1, uint32_t addr) {
    asm volatile("ldmatrix.sync.aligned.m8n8.x2.trans.shared.b16 {%0,%1}, [%2];"
        : "=r"(r0), "=r"(r1) : "r"(addr));
}
__device__ __forceinline__ void mma16816(float* c, const uint32_t* a, uint32_t b0, uint32_t b1) {
    asm volatile("mma.sync.aligned.m16n8k16.row.col.f32.f16.f16.f32 "
        "{%0,%1,%2,%3}, {%4,%5,%6,%7}, {%8,%9}, {%0,%1,%2,%3};"
        : "+f"(c[0]), "+f"(c[1]), "+f"(c[2]), "+f"(c[3])
        : "r"(a[0]), "r"(a[1]), "r"(a[2]), "r"(a[3]), "r"(b0), "r"(b1));
}
__device__ __forceinline__ void cpa16(uint32_t dst, const void* src) {
    asm volatile("cp.async.cg.shared.global [%0], [%1], 16;" :: "r"(dst), "l"(src));
}
__device__ __forceinline__ void cpa16z(uint32_t dst, const void* src, int sz) {
    asm volatile("cp.async.cg.shared.global [%0], [%1], 16, %2;" :: "r"(dst), "l"(src), "r"(sz));
}
__device__ __forceinline__ void cpa_commit() {
    asm volatile("cp.async.commit_group;" ::: "memory");
}
template <int N>
__device__ __forceinline__ void cpa_wait() {
    asm volatile("cp.async.wait_group %0;" :: "n"(N) : "memory");
}
__device__ __forceinline__ void pipe_wait(int c) {
    if (c + 2 < NC)      cpa_wait<2>();
    else if (c + 1 < NC) cpa_wait<1>();
    else                 cpa_wait<0>();
}
__device__ __forceinline__ void red_add_v2(float* p, float v0, float v1) {
    asm volatile("red.global.add.v2.f32 [%0], {%1, %2};"
        :: "l"(p), "f"(v0), "f"(v1) : "memory");
}

// ---------------- small kernels ----------------
__global__ void cvt_x_init_kernel(const float* __restrict__ s, __half* __restrict__ d,
                                  float* __restrict__ y, size_t n4) {
    size_t i = (size_t)blockIdx.x * blockDim.x + threadIdx.x;
    if (i < n4) {
        float4 v = reinterpret_cast<const float4*>(s)[i];
        reinterpret_cast<__half2*>(d)[2 * i]     = __floats2half2_rn(v.x, v.y);
        reinterpret_cast<__half2*>(d)[2 * i + 1] = __floats2half2_rn(v.z, v.w);
        float4 z = {0.f, 0.f, 0.f, 0.f};
        reinterpret_cast<float4*>(y)[i] = z;
    }
    if (blockIdx.x == 0 && threadIdx.x < EE) g_cnt[threadIdx.x] = 0;
}

__global__ void cvt_kernel(const float* __restrict__ s, __half* __restrict__ d, size_t n4) {
    size_t i = (size_t)blockIdx.x * blockDim.x + threadIdx.x;
    if (i < n4) {
        float4 v = reinterpret_cast<const float4*>(s)[i];
        reinterpret_cast<__half2*>(d)[2 * i]     = __floats2half2_rn(v.x, v.y);
        reinterpret_cast<__half2*>(d)[2 * i + 1] = __floats2half2_rn(v.z, v.w);
    }
}

// ---------------- router (float4-vectorized dot products) ----------------
__global__ void __launch_bounds__(512) router_kernel(
    const float* __restrict__ x, const float* __restrict__ wr,
    const float* __restrict__ br, float* __restrict__ scores) {
    int t = blockIdx.x;
    int lane = threadIdx.x & 31;
    int e = threadIdx.x >> 5;

    const float4* xr4 = reinterpret_cast<const float4*>(x + (size_t)t * HH);
    const float4* w4  = reinterpret_cast<const float4*>(wr + (size_t)e * HH);
    float s = 0.f;
    #pragma unroll 4
    for (int i = lane; i < HH / 4; i += 32) {
        float4 a = xr4[i], b = w4[i];
        s += a.x * b.x + a.y * b.y + a.z * b.z + a.w * b.w;
    }
    #pragma unroll
    for (int o = 16; o > 0; o >>= 1) s += __shfl_xor_sync(0xffffffffu, s, o);

    __shared__ float logit[EE];
    if (lane == 0) logit[e] = s + br[e];
    __syncthreads();

    if (threadIdx.x == 0) {
        float v[EE];
        #pragma unroll
        for (int i = 0; i < EE; i++) v[i] = logit[i];
        int bi[KTOP]; float bv[KTOP];
        #pragma unroll
        for (int k = 0; k < KTOP; k++) {
            float best = -1e30f; int b = 0;
            #pragma unroll
            for (int i = 0; i < EE; i++)
                if (v[i] > best) { best = v[i]; b = i; }
            bv[k] = best; bi[k] = b; v[b] = -1e30f;
        }
        float m = bv[0];
        float ex[KTOP], sum = 0.f;
        #pragma unroll
        for (int k = 0; k < KTOP; k++) { ex[k] = __expf(bv[k] - m); sum += ex[k]; }
        float inv = 1.f / sum;
        #pragma unroll
        for (int k = 0; k < KTOP; k++) {
            float sc = ex[k] * inv;
            if (scores) scores[t * KTOP + k] = sc * 0.25f;
            int pos = atomicAdd(&g_cnt[bi[k]], 1);
            g_rows[bi[k] * TT + pos] = t;
            g_wte[bi[k] * TT + pos]  = sc;
        }
    }
}

// ---------------- GEMM1: fp16 mma, gathered x @ Wgu -> fused GLU -----------
// BM=128, BN=64 gate + 64 up, BK=32; 8 warps 2(m)x4(n); 4-stage cp.async.
__global__ void __launch_bounds__(256, 2) gemm1_kernel(const float* __restrict__ bgu, int eBase) {
    int e = eBase + blockIdx.z;
    int cnt = g_cnt[e];
    int m0 = blockIdx.y * 128;
    if (m0 >= cnt) return;
    int n0 = blockIdx.x * 64;

    extern __shared__ __align__(16) char dyn[];
    uint32_t aBase = smem_u32(dyn + G1_A_OFF);
    uint32_t gBase = smem_u32(dyn + G1_BG_OFF);
    uint32_t uBase = smem_u32(dyn + G1_BU_OFF);
    int* tok = (int*)(dyn + G1_TOK_OFF);

    int tid = threadIdx.x, lane = tid & 31, wid = tid >> 5;
    if (tid < 128) {
        int r = m0 + tid;
        tok[tid] = (r < cnt) ? g_rows[e * TT + r] : -1;
    }
    __syncthreads();

    const __half* srcA[2]; uint32_t dstA[2]; int szA[2];
    #pragma unroll
    for (int i = 0; i < 2; i++) {
        int q = tid + i * 256, row = q >> 2, c4 = q & 3;
        int t = tok[row];
        szA[i] = (t >= 0) ? 16 : 0;
        if (t < 0) t = 0;
        srcA[i] = g_xh + (size_t)t * HH + c4 * 8;
        dstA[i] = aBase + (uint32_t)(row * 80 + c4 * 16);
    }
    int bk_ = tid >> 3, bc = tid & 7;
    uint32_t dstB = (uint32_t)(bk_ * 128 + ((bc ^ (bk_ & 7)) << 4));
    const __half* srcBg = g_wguH + ((size_t)e * HH + bk_) * (2 * DD) + n0 + bc * 8;
    const __half* srcBu = srcBg + DD;

    int wm = wid >> 2, wn = wid & 3;
    float accg[4][2][4] = {}, accu[4][2][4] = {};

    uint32_t aRow = (uint32_t)((lane & 15) * 80 + (lane >> 4) * 16);
    int kl = lane & 15, klx = kl & 7;
    uint32_t bRow = (uint32_t)(kl * 128);

    #pragma unroll
    for (int s = 0; s < 3; s++) {
        #pragma unroll
        for (int i = 0; i < 2; i++)
            cpa16z(dstA[i] + s * 10240, srcA[i] + (size_t)s * BK, szA[i]);
        cpa16(gBase + s * 4096 + dstB, srcBg + (size_t)s * BK * (2 * DD));
        cpa16(uBase + s * 4096 + dstB, srcBu + (size_t)s * BK * (2 * DD));
        cpa_commit();
    }

    for (int c = 0; c < NC; c++) {
        pipe_wait(c);
        __syncthreads();
        int buf = c & 3;
        uint32_t aS = aBase + buf * 10240;
        uint32_t gS = gBase + buf * 4096;
        uint32_t uS = uBase + buf * 4096;

        #pragma unroll
        for (int ks = 0; ks < 2; ks++) {
            uint32_t a[4][4];
            #pragma unroll
            for (int mt = 0; mt < 4; mt++)
                ldsm4(a[mt], aS + (uint32_t)((wm * 64 + mt * 16) * 80 + ks * 32) + aRow);
            #pragma unroll
            for (int nt = 0; nt < 2; nt++) {
                int cn = wn * 2 + nt;
                uint32_t sw = (uint32_t)(((cn ^ klx) << 4) + ks * 2048) + bRow;
                uint32_t bg0, bg1, bu0, bu1;
                ldsm2t(bg0, bg1, gS + sw);
                ldsm2t(bu0, bu1, uS + sw);
                #pragma unroll
                for (int mt = 0; mt < 4; mt++) {
                    mma16816(accg[mt][nt], a[mt], bg0, bg1);
                    mma16816(accu[mt][nt], a[mt], bu0, bu1);
                }
            }
        }

        int nc_ = c + 3;
        if (nc_ < NC) {
            int s = nc_ & 3;
            #pragma unroll
            for (int i = 0; i < 2; i++)
                cpa16z(dstA[i] + s * 10240, srcA[i] + (size_t)nc_ * BK, szA[i]);
            cpa16(gBase + s * 4096 + dstB, srcBg + (size_t)nc_ * BK * (2 * DD));
            cpa16(uBase + s * 4096 + dstB, srcBu + (size_t)nc_ * BK * (2 * DD));
            cpa_commit();
        }
    }

    int gid = lane >> 2, qt = lane & 3;
    const float* bgp = bgu + (size_t)e * (2 * DD) + n0;
    #pragma unroll
    for (int mt = 0; mt < 4; mt++) {
        #pragma unroll
        for (int i = 0; i < 2; i++) {
            int row = m0 + wm * 64 + mt * 16 + gid + i * 8;
            __half* orow = g_gatedH + ((size_t)e * TT + row) * DD + n0;
            #pragma unroll
            for (int nt = 0; nt < 2; nt++) {
                int col = wn * 16 + nt * 8 + 2 * qt;
                float g0 = accg[mt][nt][i * 2 + 0] + bgp[col];
                float g1 = accg[mt][nt][i * 2 + 1] + bgp[col + 1];
                float u0 = accu[mt][nt][i * 2 + 0] + bgp[DD + col];
                float u1 = accu[mt][nt][i * 2 + 1] + bgp[DD + col + 1];
                g0 = fminf(g0, LIMIT_C); g1 = fminf(g1, LIMIT_C);
                u0 = fminf(fmaxf(u0, -LIMIT_C), LIMIT_C);
                u1 = fminf(fmaxf(u1, -LIMIT_C), LIMIT_C);
                float o0 = (u0 + 1.f) * (g0 / (1.f + __expf(-ALPHA_C * g0)));
                float o1 = (u1 + 1.f) * (g1 / (1.f + __expf(-ALPHA_C * g1)));
                *reinterpret_cast<__half2*>(orow + col) = __floats2half2_rn(o0, o1);
            }
        }
    }
}

// ---------------- GEMM2: fp16 mma, gated @ Wd -> weighted red-add into y ---
// BM=128, BN=128, BK=32; 8 warps 2(m)x4(n); 4-stage cp.async.
__global__ void __launch_bounds__(256, 2) gemm2_kernel(
    const float* __restrict__ bd, float* __restrict__ y) {
    int e = blockIdx.z;
    int cnt = g_cnt[e];
    int m0 = blockIdx.y * 128;
    if (m0 >= cnt) return;
    int n0 = blockIdx.x * 128;

    extern __shared__ __align__(16) char dyn[];
    uint32_t aBase = smem_u32(dyn + G2_A_OFF);
    uint32_t bBase = smem_u32(dyn + G2_B_OFF);
    int*   tok = (int*)(dyn + G2_TOK_OFF);
    float* wts = (float*)(dyn + G2_WTS_OFF);

    int tid = threadIdx.x, lane = tid & 31, wid = tid >> 5;
    if (tid < 128) {
        int r = m0 + tid;
        if (r < cnt) { tok[tid] = g_rows[e * TT + r]; wts[tid] = g_wte[e * TT + r]; }
        else         { tok[tid] = 0; wts[tid] = 0.f; }
    }
    __syncthreads();

    const __half* srcA[2]; uint32_t dstA[2];
    #pragma unroll
    for (int i = 0; i < 2; i++) {
        int q = tid + i * 256, row = q >> 2, c4 = q & 3;
        srcA[i] = g_gatedH + ((size_t)e * TT + m0 + row) * DD + c4 * 8;
        dstA[i] = aBase + (uint32_t)(row * 80 + c4 * 16);
    }
    const __half* srcB[2]; uint32_t dstB[2];
    #pragma unroll
    for (int i = 0; i < 2; i++) {
        int q = tid + i * 256, k = q >> 4, c = q & 15;
        srcB[i] = g_dpH + ((size_t)e * DD + k) * HH + n0 + c * 8;
        dstB[i] = bBase + (uint32_t)(k * 256 + ((c ^ (k & 7)) << 4));
    }

    int wm = wid >> 2, wn = wid & 3;
    float acc[4][4][4] = {};

    uint32_t aRow = (uint32_t)((lane & 15) * 80 + (lane >> 4) * 16);
    int kl = lane & 15, klx = kl & 7;
    uint32_t bRow = (uint32_t)(kl * 256);

    #pragma unroll
    for (int s = 0; s < 3; s++) {
        #pragma unroll
        for (int i = 0; i < 2; i++)
            cpa16(dstA[i] + s * 10240, srcA[i] + (size_t)s * BK);
        #pragma unroll
        for (int i = 0; i < 2; i++)
            cpa16(dstB[i] + s * 8192, srcB[i] + (size_t)s * BK * HH);
        cpa_commit();
    }

    for (int c = 0; c < NC; c++) {
        pipe_wait(c);
        __syncthreads();
        int buf = c & 3;
        uint32_t aS = aBase + buf * 10240;
        uint32_t bS = bBase + buf * 8192;

        #pragma unroll
        for (int ks = 0; ks < 2; ks++) {
            uint32_t a[4][4];
            #pragma unroll
            for (int mt = 0; mt < 4; mt++)
                ldsm4(a[mt], aS + (uint32_t)((wm * 64 + mt * 16) * 80 + ks * 32) + aRow);
            #pragma unroll
            for (int nt = 0; nt < 4; nt++) {
                int cn = wn * 4 + nt;
                uint32_t sw = (uint32_t)(((cn ^ klx) << 4) + ks * 4096) + bRow;
                uint32_t b0, b1;
                ldsm2t(b0, b1, bS + sw);
                #pragma unroll
                for (int mt = 0; mt < 4; mt++)
                    mma16816(acc[mt][nt], a[mt], b0, b1);
            }
        }

        int nc_ = c + 3;
        if (nc_ < NC) {
            int s = nc_ & 3;
            #pragma unroll
            for (int i = 0; i < 2; i++)
                cpa16(dstA[i] + s * 10240, srcA[i] + (size_t)nc_ * BK);
            #pragma unroll
            for (int i = 0; i < 2; i++)
                cpa16(dstB[i] + s * 8192, srcB[i] + (size_t)nc_ * BK * HH);
            cpa_commit();
        }
    }

    int gid = lane >> 2, qt = lane & 3;
    const float* bdp = bd + (size_t)e * HH + n0;
    #pragma unroll
    for (int mt = 0; mt < 4; mt++) {
        #pragma unroll
        for (int i = 0; i < 2; i++) {
            int slot = wm * 64 + mt * 16 + gid + i * 8;
            if (m0 + slot < cnt) {
                float w = wts[slot];
                int t = tok[slot];
                float* yrow = y + (size_t)t * HH + n0;
                #pragma unroll
                for (int nt = 0; nt < 4; nt++) {
                    int col = wn * 32 + nt * 8 + 2 * qt;
                    float v0 = (acc[mt][nt][i * 2 + 0] + bdp[col])     * w;
                    float v1 = (acc[mt][nt][i * 2 + 1] + bdp[col + 1]) * w;
                    red_add_v2(yrow + col, v0, v1);
                }
            }
        }
    }
}

// ---------------- launch ----------------
extern "C" void kernel_launch(void* const* d_in, const int* in_sizes, int n_in,
                              void* d_out, int out_size) {
    const float* x   = (const float*)d_in[0];
    const float* wr  = (const float*)d_in[1];
    const float* br  = (const float*)d_in[2];
    const float* wgu = (const float*)d_in[3];
    const float* bgu = (const float*)d_in[4];
    const float* dp  = (const float*)d_in[5];
    const float* bd  = (const float*)d_in[6];
    (void)in_sizes; (void)n_in;

    float* y = (float*)d_out;
    float* scores = nullptr;
    if ((size_t)out_size >= (size_t)TT * HH + (size_t)TT * KTOP)
        scores = y + (size_t)TT * HH;

    static cudaStream_t s1 = nullptr, s2 = nullptr;
    static cudaEvent_t evR = nullptr, ev1a = nullptr, ev1b = nullptr, ev2 = nullptr, evDone = nullptr;
    static bool inited = false;
    if (!inited) {
        cudaFuncSetAttribute(gemm1_kernel, cudaFuncAttributeMaxDynamicSharedMemorySize, G1_SMEM);
        cudaFuncSetAttribute(gemm2_kernel, cudaFuncAttributeMaxDynamicSharedMemorySize, G2_SMEM);
        cudaStreamCreateWithFlags(&s1, cudaStreamNonBlocking);
        cudaStreamCreateWithFlags(&s2, cudaStreamNonBlocking);
        cudaEventCreateWithFlags(&evR,   cudaEventDisableTiming);
        cudaEventCreateWithFlags(&ev1a,  cudaEventDisableTiming);
        cudaEventCreateWithFlags(&ev1b,  cudaEventDisableTiming);
        cudaEventCreateWithFlags(&ev2,   cudaEventDisableTiming);
        cudaEventCreateWithFlags(&evDone, cudaEventDisableTiming);
        inited = true;
    }

    __half* xh;   cudaGetSymbolAddress((void**)&xh,   g_xh);
    __half* wguH; cudaGetSymbolAddress((void**)&wguH, g_wguH);
    __half* dpH;  cudaGetSymbolAddress((void**)&dpH,  g_dpH);

    // fork side streams off the capture stream
    cudaEventRecord(evR, 0);
    cudaStreamWaitEvent(s1, evR, 0);
    cudaStreamWaitEvent(s2, evR, 0);

    // s1: gate_up weight conversion in two expert-halves (gemm1 halves gate on each)
    size_t n4h = (size_t)EH * HH * (2 * DD) / 4;     // one half, in float4 units
    cvt_kernel<<<(int)((n4h + 255) / 256), 256, 0, s1>>>(wgu, wguH, n4h);
    cudaEventRecord(ev1a, s1);
    cvt_kernel<<<(int)((n4h + 255) / 256), 256, 0, s1>>>(wgu + n4h * 4, wguH + n4h * 4, n4h);
    cudaEventRecord(ev1b, s1);

    // main stream: x conversion + y zero + counter init, then router
    {
        size_t n4 = (size_t)TT * HH / 4;
        cvt_x_init_kernel<<<(int)((n4 + 255) / 256), 256>>>(x, xh, y, n4);
    }
    router_kernel<<<TT, 512>>>(x, wr, br, scores);

    // s2: down-proj conversion AFTER wgu is fully converted -> runs under gemm1,
    // using DRAM bandwidth that gemm1 (compute-bound) leaves idle.
    cudaStreamWaitEvent(s2, ev1b, 0);
    {
        size_t n4 = (size_t)EE * DD * HH / 4;
        cvt_kernel<<<(int)((n4 + 255) / 256), 256, 0, s2>>>(dp, dpH, n4);
        cudaEventRecord(ev2, s2);
    }

    // gemm1 in two half-launches on the main stream, each gated on its cvt half
    dim3 g1(DD / 64, TT / 128, EH);
    cudaStreamWaitEvent(0, ev1a, 0);
    gemm1_kernel<<<g1, 256, G1_SMEM>>>(bgu, 0);
    cudaStreamWaitEvent(0, ev1b, 0);
    gemm1_kernel<<<g1, 256, G1_SMEM>>>(bgu, EH);

    // gemm2: single launch on main stream (needs gemm1 done + dp converted)
    cudaStreamWaitEvent(0, ev2, 0);
    dim3 g2(HH / 128, TT / 128, EE);
    gemm2_kernel<<<g2, 256, G2_SMEM>>>(bd, y);
}

// round 16
// speedup vs baseline: 1.0115x; 1.0115x over previous
#include <cuda_runtime.h>
#include <cuda_fp16.h>
#include <cstdint>

#define TT 4096
#define HH 2048
#define DD 2048
#define EE 16
#define KTOP 4
#define ALPHA_C 1.702f
#define LIMIT_C 7.0f
#define BK 32
#define NC (HH / BK)     // 64 (HH == DD)

// GEMM1 dynamic smem: A 4*10240, Bg 4*4096, Bu 4*4096, tok 512
#define G1_A_OFF   0
#define G1_BG_OFF  (4 * 10240)
#define G1_BU_OFF  (G1_BG_OFF + 4 * 4096)
#define G1_TOK_OFF (G1_BU_OFF + 4 * 4096)
#define G1_SMEM    (G1_TOK_OFF + 512)
// GEMM2 dynamic smem: A 4*10240, B 4*8192, tok 512, wts 512
#define G2_A_OFF   0
#define G2_B_OFF   (4 * 10240)
#define G2_TOK_OFF (G2_B_OFF + 4 * 8192)
#define G2_WTS_OFF (G2_TOK_OFF + 512)
#define G2_SMEM    (G2_WTS_OFF + 512)

// ---------------- device scratch ----------------
__device__ int    g_cnt[EE];
__device__ int    g_rows[EE * TT];
__device__ float  g_wte[EE * TT];       // combine weight per (expert, slot)
__device__ __half g_xh[(size_t)TT * HH];
__device__ __half g_wguH[(size_t)EE * HH * (2 * DD)];
__device__ __half g_dpH[(size_t)EE * DD * HH];
__device__ __half g_gatedH[(size_t)EE * TT * DD];

// ---------------- helpers ----------------
__device__ __forceinline__ uint32_t smem_u32(const void* p) {
    uint32_t a;
    asm("{ .reg .u64 t; cvta.to.shared.u64 t, %1; cvt.u32.u64 %0, t; }" : "=r"(a) : "l"(p));
    return a;
}
__device__ __forceinline__ void ldsm4(uint32_t* r, uint32_t addr) {
    asm volatile("ldmatrix.sync.aligned.m8n8.x4.shared.b16 {%0,%1,%2,%3}, [%4];"
        : "=r"(r[0]), "=r"(r[1]), "=r"(r[2]), "=r"(r[3]) : "r"(addr));
}
__device__ __forceinline__ void ldsm2t(uint32_t& r0, uint32_t& r1, uint32_t addr) {
    asm volatile("ldmatrix.sync.aligned.m8n8.x2.trans.shared.b16 {%0,%1}, [%2];"
        : "=r"(r0), "=r"(r1) : "r"(addr));
}
__device__ __forceinline__ void mma16816(float* c, const uint32_t* a, uint32_t b0, uint32_t b1) {
    asm volatile("mma.sync.aligned.m16n8k16.row.col.f32.f16.f16.f32 "
        "{%0,%1,%2,%3}, {%4,%5,%6,%7}, {%8,%9}, {%0,%1,%2,%3};"
        : "+f"(c[0]), "+f"(c[1]), "+f"(c[2]), "+f"(c[3])
        : "r"(a[0]), "r"(a[1]), "r"(a[2]), "r"(a[3]), "r"(b0), "r"(b1));
}
__device__ __forceinline__ void cpa16(uint32_t dst, const void* src) {
    asm volatile("cp.async.cg.shared.global [%0], [%1], 16;" :: "r"(dst), "l"(src));
}
__device__ __forceinline__ void cpa16z(uint32_t dst, const void* src, int sz) {
    asm volatile("cp.async.cg.shared.global [%0], [%1], 16, %2;" :: "r"(dst), "l"(src), "r"(sz));
}
__device__ __forceinline__ void cpa_commit() {
    asm volatile("cp.async.commit_group;" ::: "memory");
}
template <int N>
__device__ __forceinline__ void cpa_wait() {
    asm volatile("cp.async.wait_group %0;" :: "n"(N) : "memory");
}
__device__ __forceinline__ void pipe_wait(int c) {
    if (c + 2 < NC)      cpa_wait<2>();
    else if (c + 1 < NC) cpa_wait<1>();
    else                 cpa_wait<0>();
}
__device__ __forceinline__ void red_add_v2(float* p, float v0, float v1) {
    asm volatile("red.global.add.v2.f32 [%0], {%1, %2};"
        :: "l"(p), "f"(v0), "f"(v1) : "memory");
}

// ---------------- small kernels ----------------
// converts x -> fp16, zeroes y, inits counters
__global__ void cvt_x_init_kernel(const float* __restrict__ s, __half* __restrict__ d,
                                  float* __restrict__ y, size_t n4) {
    size_t i = (size_t)blockIdx.x * blockDim.x + threadIdx.x;
    if (i < n4) {
        float4 v = reinterpret_cast<const float4*>(s)[i];
        reinterpret_cast<__half2*>(d)[2 * i]     = __floats2half2_rn(v.x, v.y);
        reinterpret_cast<__half2*>(d)[2 * i + 1] = __floats2half2_rn(v.z, v.w);
        float4 z = {0.f, 0.f, 0.f, 0.f};
        reinterpret_cast<float4*>(y)[i] = z;
    }
    if (blockIdx.x == 0 && threadIdx.x < EE) g_cnt[threadIdx.x] = 0;
}

__global__ void cvt_kernel(const float* __restrict__ s, __half* __restrict__ d, size_t n4) {
    size_t i = (size_t)blockIdx.x * blockDim.x + threadIdx.x;
    if (i < n4) {
        float4 v = reinterpret_cast<const float4*>(s)[i];
        reinterpret_cast<__half2*>(d)[2 * i]     = __floats2half2_rn(v.x, v.y);
        reinterpret_cast<__half2*>(d)[2 * i + 1] = __floats2half2_rn(v.z, v.w);
    }
}

// ---------------- router ----------------
__global__ void __launch_bounds__(512) router_kernel(
    const float* __restrict__ x, const float* __restrict__ wr,
    const float* __restrict__ br, float* __restrict__ scores) {
    int t = blockIdx.x;
    int lane = threadIdx.x & 31;
    int e = threadIdx.x >> 5;

    const float* xr = x + (size_t)t * HH;
    const float* w  = wr + (size_t)e * HH;
    float s = 0.f;
    for (int i = lane; i < HH; i += 32) s += xr[i] * w[i];
    #pragma unroll
    for (int o = 16; o > 0; o >>= 1) s += __shfl_xor_sync(0xffffffffu, s, o);

    __shared__ float logit[EE];
    if (lane == 0) logit[e] = s + br[e];
    __syncthreads();

    if (threadIdx.x == 0) {
        float v[EE];
        #pragma unroll
        for (int i = 0; i < EE; i++) v[i] = logit[i];
        int bi[KTOP]; float bv[KTOP];
        #pragma unroll
        for (int k = 0; k < KTOP; k++) {
            float best = -1e30f; int b = 0;
            #pragma unroll
            for (int i = 0; i < EE; i++)
                if (v[i] > best) { best = v[i]; b = i; }
            bv[k] = best; bi[k] = b; v[b] = -1e30f;
        }
        float m = bv[0];
        float ex[KTOP], sum = 0.f;
        #pragma unroll
        for (int k = 0; k < KTOP; k++) { ex[k] = __expf(bv[k] - m); sum += ex[k]; }
        float inv = 1.f / sum;
        #pragma unroll
        for (int k = 0; k < KTOP; k++) {
            float sc = ex[k] * inv;
            if (scores) scores[t * KTOP + k] = sc * 0.25f;
            int pos = atomicAdd(&g_cnt[bi[k]], 1);
            g_rows[bi[k] * TT + pos] = t;
            g_wte[bi[k] * TT + pos]  = sc;
        }
    }
}

// ---------------- GEMM1: fp16 mma, gathered x @ Wgu -> fused GLU -----------
// BM=128, BN=64 gate + 64 up, BK=32; 8 warps 2(m)x4(n); 4-stage cp.async.
__global__ void __launch_bounds__(256, 2) gemm1_kernel(const float* __restrict__ bgu) {
    int e = blockIdx.z;
    int cnt = g_cnt[e];
    int m0 = blockIdx.y * 128;
    if (m0 >= cnt) return;
    int n0 = blockIdx.x * 64;

    extern __shared__ __align__(16) char dyn[];
    uint32_t aBase = smem_u32(dyn + G1_A_OFF);
    uint32_t gBase = smem_u32(dyn + G1_BG_OFF);
    uint32_t uBase = smem_u32(dyn + G1_BU_OFF);
    int* tok = (int*)(dyn + G1_TOK_OFF);

    int tid = threadIdx.x, lane = tid & 31, wid = tid >> 5;
    if (tid < 128) {
        int r = m0 + tid;
        tok[tid] = (r < cnt) ? g_rows[e * TT + r] : -1;
    }
    __syncthreads();

    const __half* srcA[2]; uint32_t dstA[2]; int szA[2];
    #pragma unroll
    for (int i = 0; i < 2; i++) {
        int q = tid + i * 256, row = q >> 2, c4 = q & 3;
        int t = tok[row];
        szA[i] = (t >= 0) ? 16 : 0;
        if (t < 0) t = 0;
        srcA[i] = g_xh + (size_t)t * HH + c4 * 8;
        dstA[i] = aBase + (uint32_t)(row * 80 + c4 * 16);
    }
    int bk_ = tid >> 3, bc = tid & 7;
    uint32_t dstB = (uint32_t)(bk_ * 128 + ((bc ^ (bk_ & 7)) << 4));
    const __half* srcBg = g_wguH + ((size_t)e * HH + bk_) * (2 * DD) + n0 + bc * 8;
    const __half* srcBu = srcBg + DD;

    int wm = wid >> 2, wn = wid & 3;
    float accg[4][2][4] = {}, accu[4][2][4] = {};

    uint32_t aRow = (uint32_t)((lane & 15) * 80 + (lane >> 4) * 16);
    int kl = lane & 15, klx = kl & 7;
    uint32_t bRow = (uint32_t)(kl * 128);

    #pragma unroll
    for (int s = 0; s < 3; s++) {
        #pragma unroll
        for (int i = 0; i < 2; i++)
            cpa16z(dstA[i] + s * 10240, srcA[i] + (size_t)s * BK, szA[i]);
        cpa16(gBase + s * 4096 + dstB, srcBg + (size_t)s * BK * (2 * DD));
        cpa16(uBase + s * 4096 + dstB, srcBu + (size_t)s * BK * (2 * DD));
        cpa_commit();
    }

    for (int c = 0; c < NC; c++) {
        pipe_wait(c);
        __syncthreads();
        int buf = c & 3;
        uint32_t aS = aBase + buf * 10240;
        uint32_t gS = gBase + buf * 4096;
        uint32_t uS = uBase + buf * 4096;

        #pragma unroll
        for (int ks = 0; ks < 2; ks++) {
            uint32_t a[4][4];
            #pragma unroll
            for (int mt = 0; mt < 4; mt++)
                ldsm4(a[mt], aS + (uint32_t)((wm * 64 + mt * 16) * 80 + ks * 32) + aRow);
            #pragma unroll
            for (int nt = 0; nt < 2; nt++) {
                int cn = wn * 2 + nt;
                uint32_t sw = (uint32_t)(((cn ^ klx) << 4) + ks * 2048) + bRow;
                uint32_t bg0, bg1, bu0, bu1;
                ldsm2t(bg0, bg1, gS + sw);
                ldsm2t(bu0, bu1, uS + sw);
                #pragma unroll
                for (int mt = 0; mt < 4; mt++) {
                    mma16816(accg[mt][nt], a[mt], bg0, bg1);
                    mma16816(accu[mt][nt], a[mt], bu0, bu1);
                }
            }
        }

        int nc_ = c + 3;
        if (nc_ < NC) {
            int s = nc_ & 3;
            #pragma unroll
            for (int i = 0; i < 2; i++)
                cpa16z(dstA[i] + s * 10240, srcA[i] + (size_t)nc_ * BK, szA[i]);
            cpa16(gBase + s * 4096 + dstB, srcBg + (size_t)nc_ * BK * (2 * DD));
            cpa16(uBase + s * 4096 + dstB, srcBu + (size_t)nc_ * BK * (2 * DD));
            cpa_commit();
        }
    }

    int gid = lane >> 2, qt = lane & 3;
    const float* bgp = bgu + (size_t)e * (2 * DD) + n0;
    #pragma unroll
    for (int mt = 0; mt < 4; mt++) {
        #pragma unroll
        for (int i = 0; i < 2; i++) {
            int row = m0 + wm * 64 + mt * 16 + gid + i * 8;
            __half* orow = g_gatedH + ((size_t)e * TT + row) * DD + n0;
            #pragma unroll
            for (int nt = 0; nt < 2; nt++) {
                int col = wn * 16 + nt * 8 + 2 * qt;
                float g0 = accg[mt][nt][i * 2 + 0] + bgp[col];
                float g1 = accg[mt][nt][i * 2 + 1] + bgp[col + 1];
                float u0 = accu[mt][nt][i * 2 + 0] + bgp[DD + col];
                float u1 = accu[mt][nt][i * 2 + 1] + bgp[DD + col + 1];
                g0 = fminf(g0, LIMIT_C); g1 = fminf(g1, LIMIT_C);
                u0 = fminf(fmaxf(u0, -LIMIT_C), LIMIT_C);
                u1 = fminf(fmaxf(u1, -LIMIT_C), LIMIT_C);
                float o0 = (u0 + 1.f) * (g0 / (1.f + __expf(-ALPHA_C * g0)));
                float o1 = (u1 + 1.f) * (g1 / (1.f + __expf(-ALPHA_C * g1)));
                *reinterpret_cast<__half2*>(orow + col) = __floats2half2_rn(o0, o1);
            }
        }
    }
}

// ---------------- GEMM2: fp16 mma, gated @ Wd -> weighted red-add into y ---
// BM=128, BN=128, BK=32; 8 warps 2(m)x4(n); 4-stage cp.async.
__global__ void __launch_bounds__(256, 2) gemm2_kernel(
    const float* __restrict__ bd, float* __restrict__ y) {
    int e = blockIdx.z;
    int cnt = g_cnt[e];
    int m0 = blockIdx.y * 128;
    if (m0 >= cnt) return;
    int n0 = blockIdx.x * 128;

    extern __shared__ __align__(16) char dyn[];
    uint32_t aBase = smem_u32(dyn + G2_A_OFF);
    uint32_t bBase = smem_u32(dyn + G2_B_OFF);
    int*   tok = (int*)(dyn + G2_TOK_OFF);
    float* wts = (float*)(dyn + G2_WTS_OFF);

    int tid = threadIdx.x, lane = tid & 31, wid = tid >> 5;
    if (tid < 128) {
        int r = m0 + tid;
        if (r < cnt) { tok[tid] = g_rows[e * TT + r]; wts[tid] = g_wte[e * TT + r]; }
        else         { tok[tid] = 0; wts[tid] = 0.f; }
    }
    __syncthreads();

    const __half* srcA[2]; uint32_t dstA[2];
    #pragma unroll
    for (int i = 0; i < 2; i++) {
        int q = tid + i * 256, row = q >> 2, c4 = q & 3;
        srcA[i] = g_gatedH + ((size_t)e * TT + m0 + row) * DD + c4 * 8;
        dstA[i] = aBase + (uint32_t)(row * 80 + c4 * 16);
    }
    const __half* srcB[2]; uint32_t dstB[2];
    #pragma unroll
    for (int i = 0; i < 2; i++) {
        int q = tid + i * 256, k = q >> 4, c = q & 15;
        srcB[i] = g_dpH + ((size_t)e * DD + k) * HH + n0 + c * 8;
        dstB[i] = bBase + (uint32_t)(k * 256 + ((c ^ (k & 7)) << 4));
    }

    int wm = wid >> 2, wn = wid & 3;
    float acc[4][4][4] = {};

    uint32_t aRow = (uint32_t)((lane & 15) * 80 + (lane >> 4) * 16);
    int kl = lane & 15, klx = kl & 7;
    uint32_t bRow = (uint32_t)(kl * 256);

    #pragma unroll
    for (int s = 0; s < 3; s++) {
        #pragma unroll
        for (int i = 0; i < 2; i++)
            cpa16(dstA[i] + s * 10240, srcA[i] + (size_t)s * BK);
        #pragma unroll
        for (int i = 0; i < 2; i++)
            cpa16(dstB[i] + s * 8192, srcB[i] + (size_t)s * BK * HH);
        cpa_commit();
    }

    for (int c = 0; c < NC; c++) {
        pipe_wait(c);
        __syncthreads();
        int buf = c & 3;
        uint32_t aS = aBase + buf * 10240;
        uint32_t bS = bBase + buf * 8192;

        #pragma unroll
        for (int ks = 0; ks < 2; ks++) {
            uint32_t a[4][4];
            #pragma unroll
            for (int mt = 0; mt < 4; mt++)
                ldsm4(a[mt], aS + (uint32_t)((wm * 64 + mt * 16) * 80 + ks * 32) + aRow);
            #pragma unroll
            for (int nt = 0; nt < 4; nt++) {
                int cn = wn * 4 + nt;
                uint32_t sw = (uint32_t)(((cn ^ klx) << 4) + ks * 4096) + bRow;
                uint32_t b0, b1;
                ldsm2t(b0, b1, bS + sw);
                #pragma unroll
                for (int mt = 0; mt < 4; mt++)
                    mma16816(acc[mt][nt], a[mt], b0, b1);
            }
        }

        int nc_ = c + 3;
        if (nc_ < NC) {
            int s = nc_ & 3;
            #pragma unroll
            for (int i = 0; i < 2; i++)
                cpa16(dstA[i] + s * 10240, srcA[i] + (size_t)nc_ * BK);
            #pragma unroll
            for (int i = 0; i < 2; i++)
                cpa16(dstB[i] + s * 8192, srcB[i] + (size_t)nc_ * BK * HH);
            cpa_commit();
        }
    }

    // epilogue: (acc + bias) * w, reduce directly into y (L2-resident, 32 MB)
    int gid = lane >> 2, qt = lane & 3;
    const float* bdp = bd + (size_t)e * HH + n0;
    #pragma unroll
    for (int mt = 0; mt < 4; mt++) {
        #pragma unroll
        for (int i = 0; i < 2; i++) {
            int slot = wm * 64 + mt * 16 + gid + i * 8;
            if (m0 + slot < cnt) {
                float w = wts[slot];
                int t = tok[slot];
                float* yrow = y + (size_t)t * HH + n0;
                #pragma unroll
                for (int nt = 0; nt < 4; nt++) {
                    int col = wn * 32 + nt * 8 + 2 * qt;
                    float v0 = (acc[mt][nt][i * 2 + 0] + bdp[col])     * w;
                    float v1 = (acc[mt][nt][i * 2 + 1] + bdp[col + 1]) * w;
                    red_add_v2(yrow + col, v0, v1);
                }
            }
        }
    }
}

// ---------------- launch ----------------
extern "C" void kernel_launch(void* const* d_in, const int* in_sizes, int n_in,
                              void* d_out, int out_size) {
    const float* x   = (const float*)d_in[0];
    const float* wr  = (const float*)d_in[1];
    const float* br  = (const float*)d_in[2];
    const float* wgu = (const float*)d_in[3];
    const float* bgu = (const float*)d_in[4];
    const float* dp  = (const float*)d_in[5];
    const float* bd  = (const float*)d_in[6];
    (void)in_sizes; (void)n_in;

    float* y = (float*)d_out;
    float* scores = nullptr;
    if ((size_t)out_size >= (size_t)TT * HH + (size_t)TT * KTOP)
        scores = y + (size_t)TT * HH;

    static cudaStream_t s1 = nullptr, s2 = nullptr;
    static cudaEvent_t evR = nullptr, ev1 = nullptr, ev2 = nullptr;
    static bool inited = false;
    if (!inited) {
        cudaFuncSetAttribute(gemm1_kernel, cudaFuncAttributeMaxDynamicSharedMemorySize, G1_SMEM);
        cudaFuncSetAttribute(gemm2_kernel, cudaFuncAttributeMaxDynamicSharedMemorySize, G2_SMEM);
        cudaStreamCreateWithFlags(&s1, cudaStreamNonBlocking);
        cudaStreamCreateWithFlags(&s2, cudaStreamNonBlocking);
        cudaEventCreateWithFlags(&evR, cudaEventDisableTiming);
        cudaEventCreateWithFlags(&ev1, cudaEventDisableTiming);
        cudaEventCreateWithFlags(&ev2, cudaEventDisableTiming);
        inited = true;
    }

    __half* xh;   cudaGetSymbolAddress((void**)&xh,   g_xh);
    __half* wguH; cudaGetSymbolAddress((void**)&wguH, g_wguH);
    __half* dpH;  cudaGetSymbolAddress((void**)&dpH,  g_dpH);

    // fork side streams off the capture stream
    cudaEventRecord(evR, 0);
    cudaStreamWaitEvent(s1, evR, 0);
    cudaStreamWaitEvent(s2, evR, 0);

    // s1: gate_up weight conversion (needed by gemm1)
    {
        size_t n4 = (size_t)EE * HH * (2 * DD) / 4;
        cvt_kernel<<<(int)((n4 + 255) / 256), 256, 0, s1>>>(wgu, wguH, n4);
        cudaEventRecord(ev1, s1);
    }
    // s2: down-proj weight conversion (needed only by gemm2)
    {
        size_t n4 = (size_t)EE * DD * HH / 4;
        cvt_kernel<<<(int)((n4 + 255) / 256), 256, 0, s2>>>(dp, dpH, n4);
        cudaEventRecord(ev2, s2);
    }
    // main stream: x conversion + y zero + counter init, then router
    {
        size_t n4 = (size_t)TT * HH / 4;
        cvt_x_init_kernel<<<(int)((n4 + 255) / 256), 256>>>(x, xh, y, n4);
    }
    router_kernel<<<TT, 512>>>(x, wr, br, scores);

    // gemm1 needs wgu conversion
    cudaStreamWaitEvent(0, ev1, 0);
    dim3 g1(DD / 64, TT / 128, EE);
    gemm1_kernel<<<g1, 256, G1_SMEM>>>(bgu);

    // gemm2 needs gemm1 + dp conversion (+ y zeroed earlier on this stream)
    cudaStreamWaitEvent(0, ev2, 0);
    dim3 g2(HH / 128, TT / 128, EE);
    gemm2_kernel<<<g2, 256, G2_SMEM>>>(bd, y);
}

// round 17
// speedup vs baseline: 1.0256x; 1.0140x over previous
#include <cuda_runtime.h>
#include <cuda_fp16.h>
#include <cstdint>

#define TT 4096
#define HH 2048
#define DD 2048
#define EE 16
#define KTOP 4
#define RT 4             // tokens per router block
#define ALPHA_C 1.702f
#define LIMIT_C 7.0f
#define BK 32
#define NC (HH / BK)     // 64 (HH == DD)

// GEMM1 dynamic smem: A 4*10240, Bg 4*4096, Bu 4*4096, tok 512
#define G1_A_OFF   0
#define G1_BG_OFF  (4 * 10240)
#define G1_BU_OFF  (G1_BG_OFF + 4 * 4096)
#define G1_TOK_OFF (G1_BU_OFF + 4 * 4096)
#define G1_SMEM    (G1_TOK_OFF + 512)
// GEMM2 dynamic smem: A 4*10240, B 4*8192, tok 512, wts 512
#define G2_A_OFF   0
#define G2_B_OFF   (4 * 10240)
#define G2_TOK_OFF (G2_B_OFF + 4 * 8192)
#define G2_WTS_OFF (G2_TOK_OFF + 512)
#define G2_SMEM    (G2_WTS_OFF + 512)

// ---------------- device scratch ----------------
__device__ int    g_cnt[EE];
__device__ int    g_rows[EE * TT];
__device__ float  g_wte[EE * TT];       // combine weight per (expert, slot)
__device__ __half g_xh[(size_t)TT * HH];
__device__ __half g_wguH[(size_t)EE * HH * (2 * DD)];
__device__ __half g_dpH[(size_t)EE * DD * HH];
__device__ __half g_gatedH[(size_t)EE * TT * DD];

// ---------------- helpers ----------------
__device__ __forceinline__ uint32_t smem_u32(const void* p) {
    uint32_t a;
    asm("{ .reg .u64 t; cvta.to.shared.u64 t, %1; cvt.u32.u64 %0, t; }" : "=r"(a) : "l"(p));
    return a;
}
__device__ __forceinline__ void ldsm4(uint32_t* r, uint32_t addr) {
    asm volatile("ldmatrix.sync.aligned.m8n8.x4.shared.b16 {%0,%1,%2,%3}, [%4];"
        : "=r"(r[0]), "=r"(r[1]), "=r"(r[2]), "=r"(r[3]) : "r"(addr));
}
__device__ __forceinline__ void ldsm2t(uint32_t& r0, uint32_t& r1, uint32_t addr) {
    asm volatile("ldmatrix.sync.aligned.m8n8.x2.trans.shared.b16 {%0,%1}, [%2];"
        : "=r"(r0), "=r"(r1) : "r"(addr));
}
__device__ __forceinline__ void mma16816(float* c, const uint32_t* a, uint32_t b0, uint32_t b1) {
    asm volatile("mma.sync.aligned.m16n8k16.row.col.f32.f16.f16.f32 "
        "{%0,%1,%2,%3}, {%4,%5,%6,%7}, {%8,%9}, {%0,%1,%2,%3};"
        : "+f"(c[0]), "+f"(c[1]), "+f"(c[2]), "+f"(c[3])
        : "r"(a[0]), "r"(a[1]), "r"(a[2]), "r"(a[3]), "r"(b0), "r"(b1));
}
__device__ __forceinline__ void cpa16(uint32_t dst, const void* src) {
    asm volatile("cp.async.cg.shared.global [%0], [%1], 16;" :: "r"(dst), "l"(src));
}
__device__ __forceinline__ void cpa16z(uint32_t dst, const void* src, int sz) {
    asm volatile("cp.async.cg.shared.global [%0], [%1], 16, %2;" :: "r"(dst), "l"(src), "r"(sz));
}
__device__ __forceinline__ void cpa_commit() {
    asm volatile("cp.async.commit_group;" ::: "memory");
}
template <int N>
__device__ __forceinline__ void cpa_wait() {
    asm volatile("cp.async.wait_group %0;" :: "n"(N) : "memory");
}
__device__ __forceinline__ void pipe_wait(int c) {
    if (c + 2 < NC)      cpa_wait<2>();
    else if (c + 1 < NC) cpa_wait<1>();
    else                 cpa_wait<0>();
}
__device__ __forceinline__ void red_add_v2(float* p, float v0, float v1) {
    asm volatile("red.global.add.v2.f32 [%0], {%1, %2};"
        :: "l"(p), "f"(v0), "f"(v1) : "memory");
}

// ---------------- small kernels ----------------
// converts x -> fp16, zeroes y, inits counters
__global__ void cvt_x_init_kernel(const float* __restrict__ s, __half* __restrict__ d,
                                  float* __restrict__ y, size_t n4) {
    size_t i = (size_t)blockIdx.x * blockDim.x + threadIdx.x;
    if (i < n4) {
        float4 v = reinterpret_cast<const float4*>(s)[i];
        reinterpret_cast<__half2*>(d)[2 * i]     = __floats2half2_rn(v.x, v.y);
        reinterpret_cast<__half2*>(d)[2 * i + 1] = __floats2half2_rn(v.z, v.w);
        float4 z = {0.f, 0.f, 0.f, 0.f};
        reinterpret_cast<float4*>(y)[i] = z;
    }
    if (blockIdx.x == 0 && threadIdx.x < EE) g_cnt[threadIdx.x] = 0;
}

__global__ void cvt_kernel(const float* __restrict__ s, __half* __restrict__ d, size_t n4) {
    size_t i = (size_t)blockIdx.x * blockDim.x + threadIdx.x;
    if (i < n4) {
        float4 v = reinterpret_cast<const float4*>(s)[i];
        reinterpret_cast<__half2*>(d)[2 * i]     = __floats2half2_rn(v.x, v.y);
        reinterpret_cast<__half2*>(d)[2 * i + 1] = __floats2half2_rn(v.z, v.w);
    }
}

// ---------------- router: 4 tokens/block, smem-staged x, float4 ----------
__global__ void __launch_bounds__(512) router_kernel(
    const float* __restrict__ x, const float* __restrict__ wr,
    const float* __restrict__ br, float* __restrict__ scores) {
    __shared__ float4 xs[RT][HH / 4];     // 4 x 8KB = 32KB
    __shared__ float logit[RT][EE];

    int t0 = blockIdx.x * RT;
    int tid = threadIdx.x, lane = tid & 31, e = tid >> 5;

    // stage RT token rows (512 threads x 1 float4 per row)
    #pragma unroll
    for (int tk = 0; tk < RT; tk++)
        xs[tk][tid] = reinterpret_cast<const float4*>(x + (size_t)(t0 + tk) * HH)[tid];
    __syncthreads();

    const float4* w4 = reinterpret_cast<const float4*>(wr + (size_t)e * HH);
    float s[RT] = {};
    for (int i = lane; i < HH / 4; i += 32) {
        float4 b = w4[i];
        #pragma unroll
        for (int tk = 0; tk < RT; tk++) {
            float4 a = xs[tk][i];
            s[tk] += a.x * b.x + a.y * b.y + a.z * b.z + a.w * b.w;
        }
    }
    #pragma unroll
    for (int tk = 0; tk < RT; tk++) {
        #pragma unroll
        for (int o = 16; o > 0; o >>= 1) s[tk] += __shfl_xor_sync(0xffffffffu, s[tk], o);
    }
    if (lane == 0) {
        float be = br[e];
        #pragma unroll
        for (int tk = 0; tk < RT; tk++) logit[tk][e] = s[tk] + be;
    }
    __syncthreads();

    if (tid < RT) {
        int t = t0 + tid;
        float v[EE];
        #pragma unroll
        for (int i = 0; i < EE; i++) v[i] = logit[tid][i];
        int bi[KTOP]; float bv[KTOP];
        #pragma unroll
        for (int k = 0; k < KTOP; k++) {
            float best = -1e30f; int b = 0;
            #pragma unroll
            for (int i = 0; i < EE; i++)
                if (v[i] > best) { best = v[i]; b = i; }   // strict >: lowest idx on ties
            bv[k] = best; bi[k] = b; v[b] = -1e30f;
        }
        float m = bv[0];
        float ex[KTOP], sum = 0.f;
        #pragma unroll
        for (int k = 0; k < KTOP; k++) { ex[k] = __expf(bv[k] - m); sum += ex[k]; }
        float inv = 1.f / sum;
        #pragma unroll
        for (int k = 0; k < KTOP; k++) {
            float sc = ex[k] * inv;
            if (scores) scores[t * KTOP + k] = sc * 0.25f;
            int pos = atomicAdd(&g_cnt[bi[k]], 1);
            g_rows[bi[k] * TT + pos] = t;
            g_wte[bi[k] * TT + pos]  = sc;
        }
    }
}

// ---------------- GEMM1: fp16 mma, gathered x @ Wgu -> fused GLU -----------
// BM=128, BN=64 gate + 64 up, BK=32; 8 warps 2(m)x4(n); 4-stage cp.async.
__global__ void __launch_bounds__(256, 2) gemm1_kernel(const float* __restrict__ bgu) {
    int e = blockIdx.z;
    int cnt = g_cnt[e];
    int m0 = blockIdx.y * 128;
    if (m0 >= cnt) return;
    int n0 = blockIdx.x * 64;

    extern __shared__ __align__(16) char dyn[];
    uint32_t aBase = smem_u32(dyn + G1_A_OFF);
    uint32_t gBase = smem_u32(dyn + G1_BG_OFF);
    uint32_t uBase = smem_u32(dyn + G1_BU_OFF);
    int* tok = (int*)(dyn + G1_TOK_OFF);

    int tid = threadIdx.x, lane = tid & 31, wid = tid >> 5;
    if (tid < 128) {
        int r = m0 + tid;
        tok[tid] = (r < cnt) ? g_rows[e * TT + r] : -1;
    }
    __syncthreads();

    const __half* srcA[2]; uint32_t dstA[2]; int szA[2];
    #pragma unroll
    for (int i = 0; i < 2; i++) {
        int q = tid + i * 256, row = q >> 2, c4 = q & 3;
        int t = tok[row];
        szA[i] = (t >= 0) ? 16 : 0;
        if (t < 0) t = 0;
        srcA[i] = g_xh + (size_t)t * HH + c4 * 8;
        dstA[i] = aBase + (uint32_t)(row * 80 + c4 * 16);
    }
    int bk_ = tid >> 3, bc = tid & 7;
    uint32_t dstB = (uint32_t)(bk_ * 128 + ((bc ^ (bk_ & 7)) << 4));
    const __half* srcBg = g_wguH + ((size_t)e * HH + bk_) * (2 * DD) + n0 + bc * 8;
    const __half* srcBu = srcBg + DD;

    int wm = wid >> 2, wn = wid & 3;
    float accg[4][2][4] = {}, accu[4][2][4] = {};

    uint32_t aRow = (uint32_t)((lane & 15) * 80 + (lane >> 4) * 16);
    int kl = lane & 15, klx = kl & 7;
    uint32_t bRow = (uint32_t)(kl * 128);

    #pragma unroll
    for (int s = 0; s < 3; s++) {
        #pragma unroll
        for (int i = 0; i < 2; i++)
            cpa16z(dstA[i] + s * 10240, srcA[i] + (size_t)s * BK, szA[i]);
        cpa16(gBase + s * 4096 + dstB, srcBg + (size_t)s * BK * (2 * DD));
        cpa16(uBase + s * 4096 + dstB, srcBu + (size_t)s * BK * (2 * DD));
        cpa_commit();
    }

    for (int c = 0; c < NC; c++) {
        pipe_wait(c);
        __syncthreads();
        int buf = c & 3;
        uint32_t aS = aBase + buf * 10240;
        uint32_t gS = gBase + buf * 4096;
        uint32_t uS = uBase + buf * 4096;

        #pragma unroll
        for (int ks = 0; ks < 2; ks++) {
            uint32_t a[4][4];
            #pragma unroll
            for (int mt = 0; mt < 4; mt++)
                ldsm4(a[mt], aS + (uint32_t)((wm * 64 + mt * 16) * 80 + ks * 32) + aRow);
            #pragma unroll
            for (int nt = 0; nt < 2; nt++) {
                int cn = wn * 2 + nt;
                uint32_t sw = (uint32_t)(((cn ^ klx) << 4) + ks * 2048) + bRow;
                uint32_t bg0, bg1, bu0, bu1;
                ldsm2t(bg0, bg1, gS + sw);
                ldsm2t(bu0, bu1, uS + sw);
                #pragma unroll
                for (int mt = 0; mt < 4; mt++) {
                    mma16816(accg[mt][nt], a[mt], bg0, bg1);
                    mma16816(accu[mt][nt], a[mt], bu0, bu1);
                }
            }
        }

        int nc_ = c + 3;
        if (nc_ < NC) {
            int s = nc_ & 3;
            #pragma unroll
            for (int i = 0; i < 2; i++)
                cpa16z(dstA[i] + s * 10240, srcA[i] + (size_t)nc_ * BK, szA[i]);
            cpa16(gBase + s * 4096 + dstB, srcBg + (size_t)nc_ * BK * (2 * DD));
            cpa16(uBase + s * 4096 + dstB, srcBu + (size_t)nc_ * BK * (2 * DD));
            cpa_commit();
        }
    }

    int gid = lane >> 2, qt = lane & 3;
    const float* bgp = bgu + (size_t)e * (2 * DD) + n0;
    #pragma unroll
    for (int mt = 0; mt < 4; mt++) {
        #pragma unroll
        for (int i = 0; i < 2; i++) {
            int row = m0 + wm * 64 + mt * 16 + gid + i * 8;
            __half* orow = g_gatedH + ((size_t)e * TT + row) * DD + n0;
            #pragma unroll
            for (int nt = 0; nt < 2; nt++) {
                int col = wn * 16 + nt * 8 + 2 * qt;
                float g0 = accg[mt][nt][i * 2 + 0] + bgp[col];
                float g1 = accg[mt][nt][i * 2 + 1] + bgp[col + 1];
                float u0 = accu[mt][nt][i * 2 + 0] + bgp[DD + col];
                float u1 = accu[mt][nt][i * 2 + 1] + bgp[DD + col + 1];
                g0 = fminf(g0, LIMIT_C); g1 = fminf(g1, LIMIT_C);
                u0 = fminf(fmaxf(u0, -LIMIT_C), LIMIT_C);
                u1 = fminf(fmaxf(u1, -LIMIT_C), LIMIT_C);
                float o0 = (u0 + 1.f) * (g0 / (1.f + __expf(-ALPHA_C * g0)));
                float o1 = (u1 + 1.f) * (g1 / (1.f + __expf(-ALPHA_C * g1)));
                *reinterpret_cast<__half2*>(orow + col) = __floats2half2_rn(o0, o1);
            }
        }
    }
}

// ---------------- GEMM2: fp16 mma, gated @ Wd -> weighted red-add into y ---
// BM=128, BN=128, BK=32; 8 warps 2(m)x4(n); 4-stage cp.async.
__global__ void __launch_bounds__(256, 2) gemm2_kernel(
    const float* __restrict__ bd, float* __restrict__ y) {
    int e = blockIdx.z;
    int cnt = g_cnt[e];
    int m0 = blockIdx.y * 128;
    if (m0 >= cnt) return;
    int n0 = blockIdx.x * 128;

    extern __shared__ __align__(16) char dyn[];
    uint32_t aBase = smem_u32(dyn + G2_A_OFF);
    uint32_t bBase = smem_u32(dyn + G2_B_OFF);
    int*   tok = (int*)(dyn + G2_TOK_OFF);
    float* wts = (float*)(dyn + G2_WTS_OFF);

    int tid = threadIdx.x, lane = tid & 31, wid = tid >> 5;
    if (tid < 128) {
        int r = m0 + tid;
        if (r < cnt) { tok[tid] = g_rows[e * TT + r]; wts[tid] = g_wte[e * TT + r]; }
        else         { tok[tid] = 0; wts[tid] = 0.f; }
    }
    __syncthreads();

    const __half* srcA[2]; uint32_t dstA[2];
    #pragma unroll
    for (int i = 0; i < 2; i++) {
        int q = tid + i * 256, row = q >> 2, c4 = q & 3;
        srcA[i] = g_gatedH + ((size_t)e * TT + m0 + row) * DD + c4 * 8;
        dstA[i] = aBase + (uint32_t)(row * 80 + c4 * 16);
    }
    const __half* srcB[2]; uint32_t dstB[2];
    #pragma unroll
    for (int i = 0; i < 2; i++) {
        int q = tid + i * 256, k = q >> 4, c = q & 15;
        srcB[i] = g_dpH + ((size_t)e * DD + k) * HH + n0 + c * 8;
        dstB[i] = bBase + (uint32_t)(k * 256 + ((c ^ (k & 7)) << 4));
    }

    int wm = wid >> 2, wn = wid & 3;
    float acc[4][4][4] = {};

    uint32_t aRow = (uint32_t)((lane & 15) * 80 + (lane >> 4) * 16);
    int kl = lane & 15, klx = kl & 7;
    uint32_t bRow = (uint32_t)(kl * 256);

    #pragma unroll
    for (int s = 0; s < 3; s++) {
        #pragma unroll
        for (int i = 0; i < 2; i++)
            cpa16(dstA[i] + s * 10240, srcA[i] + (size_t)s * BK);
        #pragma unroll
        for (int i = 0; i < 2; i++)
            cpa16(dstB[i] + s * 8192, srcB[i] + (size_t)s * BK * HH);
        cpa_commit();
    }

    for (int c = 0; c < NC; c++) {
        pipe_wait(c);
        __syncthreads();
        int buf = c & 3;
        uint32_t aS = aBase + buf * 10240;
        uint32_t bS = bBase + buf * 8192;

        #pragma unroll
        for (int ks = 0; ks < 2; ks++) {
            uint32_t a[4][4];
            #pragma unroll
            for (int mt = 0; mt < 4; mt++)
                ldsm4(a[mt], aS + (uint32_t)((wm * 64 + mt * 16) * 80 + ks * 32) + aRow);
            #pragma unroll
            for (int nt = 0; nt < 4; nt++) {
                int cn = wn * 4 + nt;
                uint32_t sw = (uint32_t)(((cn ^ klx) << 4) + ks * 4096) + bRow;
                uint32_t b0, b1;
                ldsm2t(b0, b1, bS + sw);
                #pragma unroll
                for (int mt = 0; mt < 4; mt++)
                    mma16816(acc[mt][nt], a[mt], b0, b1);
            }
        }

        int nc_ = c + 3;
        if (nc_ < NC) {
            int s = nc_ & 3;
            #pragma unroll
            for (int i = 0; i < 2; i++)
                cpa16(dstA[i] + s * 10240, srcA[i] + (size_t)nc_ * BK);
            #pragma unroll
            for (int i = 0; i < 2; i++)
                cpa16(dstB[i] + s * 8192, srcB[i] + (size_t)nc_ * BK * HH);
            cpa_commit();
        }
    }

    // epilogue: (acc + bias) * w, reduce directly into y (L2-resident, 32 MB)
    int gid = lane >> 2, qt = lane & 3;
    const float* bdp = bd + (size_t)e * HH + n0;
    #pragma unroll
    for (int mt = 0; mt < 4; mt++) {
        #pragma unroll
        for (int i = 0; i < 2; i++) {
            int slot = wm * 64 + mt * 16 + gid + i * 8;
            if (m0 + slot < cnt) {
                float w = wts[slot];
                int t = tok[slot];
                float* yrow = y + (size_t)t * HH + n0;
                #pragma unroll
                for (int nt = 0; nt < 4; nt++) {
                    int col = wn * 32 + nt * 8 + 2 * qt;
                    float v0 = (acc[mt][nt][i * 2 + 0] + bdp[col])     * w;
                    float v1 = (acc[mt][nt][i * 2 + 1] + bdp[col + 1]) * w;
                    red_add_v2(yrow + col, v0, v1);
                }
            }
        }
    }
}

// ---------------- launch ----------------
extern "C" void kernel_launch(void* const* d_in, const int* in_sizes, int n_in,
                              void* d_out, int out_size) {
    const float* x   = (const float*)d_in[0];
    const float* wr  = (const float*)d_in[1];
    const float* br  = (const float*)d_in[2];
    const float* wgu = (const float*)d_in[3];
    const float* bgu = (const float*)d_in[4];
    const float* dp  = (const float*)d_in[5];
    const float* bd  = (const float*)d_in[6];
    (void)in_sizes; (void)n_in;

    float* y = (float*)d_out;
    float* scores = nullptr;
    if ((size_t)out_size >= (size_t)TT * HH + (size_t)TT * KTOP)
        scores = y + (size_t)TT * HH;

    static cudaStream_t s1 = nullptr, s2 = nullptr;
    static cudaEvent_t evR = nullptr, ev1 = nullptr, ev2 = nullptr;
    static bool inited = false;
    if (!inited) {
        cudaFuncSetAttribute(gemm1_kernel, cudaFuncAttributeMaxDynamicSharedMemorySize, G1_SMEM);
        cudaFuncSetAttribute(gemm2_kernel, cudaFuncAttributeMaxDynamicSharedMemorySize, G2_SMEM);
        cudaStreamCreateWithFlags(&s1, cudaStreamNonBlocking);
        cudaStreamCreateWithFlags(&s2, cudaStreamNonBlocking);
        cudaEventCreateWithFlags(&evR, cudaEventDisableTiming);
        cudaEventCreateWithFlags(&ev1, cudaEventDisableTiming);
        cudaEventCreateWithFlags(&ev2, cudaEventDisableTiming);
        inited = true;
    }

    __half* xh;   cudaGetSymbolAddress((void**)&xh,   g_xh);
    __half* wguH; cudaGetSymbolAddress((void**)&wguH, g_wguH);
    __half* dpH;  cudaGetSymbolAddress((void**)&dpH,  g_dpH);

    // fork side streams off the capture stream
    cudaEventRecord(evR, 0);
    cudaStreamWaitEvent(s1, evR, 0);
    cudaStreamWaitEvent(s2, evR, 0);

    // s1: gate_up weight conversion (needed by gemm1)
    {
        size_t n4 = (size_t)EE * HH * (2 * DD) / 4;
        cvt_kernel<<<(int)((n4 + 255) / 256), 256, 0, s1>>>(wgu, wguH, n4);
        cudaEventRecord(ev1, s1);
    }
    // s2: down-proj weight conversion (needed only by gemm2)
    {
        size_t n4 = (size_t)EE * DD * HH / 4;
        cvt_kernel<<<(int)((n4 + 255) / 256), 256, 0, s2>>>(dp, dpH, n4);
        cudaEventRecord(ev2, s2);
    }
    // main stream: x conversion + y zero + counter init, then router
    {
        size_t n4 = (size_t)TT * HH / 4;
        cvt_x_init_kernel<<<(int)((n4 + 255) / 256), 256>>>(x, xh, y, n4);
    }
    router_kernel<<<TT / RT, 512>>>(x, wr, br, scores);

    // gemm1 needs wgu conversion
    cudaStreamWaitEvent(0, ev1, 0);
    dim3 g1(DD / 64, TT / 128, EE);
    gemm1_kernel<<<g1, 256, G1_SMEM>>>(bgu);

    // gemm2 needs gemm1 + dp conversion (+ y zeroed earlier on this stream)
    cudaStreamWaitEvent(0, ev2, 0);
    dim3 g2(HH / 128, TT / 128, EE);
    gemm2_kernel<<<g2, 256, G2_SMEM>>>(bd, y);
}